// round 4
// baseline (speedup 1.0000x reference)
#include <cuda_runtime.h>
#include <cuda_bf16.h>
#include <stdint.h>

#define FULLMASK 0xFFFFFFFFu

constexpr int HWN     = 3136;   // 56*56
constexpr int NCH     = 512;
constexpr int NBATCH  = 32;
constexpr int CPB     = 8;      // channels per block (1 per warp)
constexpr int KSEL    = 627;    // round(0.2*3136)
constexpr int STRIDE  = 3140;   // smem row stride (u32), 16B aligned
constexpr int NQ      = HWN / 4;        // 784 uint4 per row
constexpr int HSTRIDE = 264;    // histogram row stride (banks offset by 8 per channel)
constexpr int SMEM_WORDS = CPB * STRIDE + CPB * HSTRIDE;
constexpr float ALPHA = 0.7f;

// monotone float -> u32 key (ascending float == ascending unsigned)
__device__ __forceinline__ unsigned f2key(unsigned b) {
    return (b & 0x80000000u) ? ~b : (b | 0x80000000u);
}
__device__ __forceinline__ float key2f(unsigned u) {
    return __uint_as_float((u & 0x80000000u) ? (u & 0x7FFFFFFFu) : ~u);
}

__device__ __forceinline__ int wredi(int v) {
#pragma unroll
    for (int d = 16; d; d >>= 1) v += __shfl_xor_sync(FULLMASK, v, d);
    return v;
}
__device__ __forceinline__ float wredf(float v) {
#pragma unroll
    for (int d = 16; d; d >>= 1) v += __shfl_xor_sync(FULLMASK, v, d);
    return v;
}

// Warp-parallel rank walk over a 256-bin histogram, rank r is 1-based FROM THE
// LARGEST bin. Counts are ((hist[i] >> shift) & 0xFFFF). Returns (bin, rankInBin).
__device__ __forceinline__ int2 walk(const unsigned* hist, int shift, int lane, int r)
{
    unsigned c[8];
    int s = 0;
#pragma unroll
    for (int j = 0; j < 8; j++) {
        c[j] = (hist[lane * 8 + j] >> shift) & 0xFFFFu;
        s += (int)c[j];
    }
    // inclusive suffix sum across lanes (sum over lanes >= lane)
    int incl = s;
#pragma unroll
    for (int d = 1; d < 32; d <<= 1) {
        int v = __shfl_down_sync(FULLMASK, incl, d);
        if (lane + d < 32) incl += v;
    }
    int hi = incl - s;                      // count in bins above this lane's 8
    bool sel = (hi < r) && (r <= hi + s);
    unsigned bal = __ballot_sync(FULLMASK, sel);
    int L = __ffs((int)bal) - 1;
    int bin = -1, rr = 0;
    if (lane == L) {
        int rloc = r - hi;
        int cum = 0;
#pragma unroll
        for (int j = 7; j >= 0; j--) {      // from largest bin within lane
            if (bin < 0 && rloc <= cum + (int)c[j]) { bin = j; rr = rloc - cum; }
            cum += (int)c[j];
        }
        bin += lane * 8;
    }
    bin = __shfl_sync(FULLMASK, bin, L);
    rr  = __shfl_sync(FULLMASK, rr,  L);
    return make_int2(bin, rr);
}

extern __shared__ unsigned smem[];

__global__ void __launch_bounds__(256, 2)
wildcat_kernel(const float* __restrict__ x, float* __restrict__ out)
{
    unsigned* keys = smem;                   // CPB * STRIDE
    unsigned* hist = smem + CPB * STRIDE;    // CPB * HSTRIDE

    const int t    = threadIdx.x;
    const int lane = t & 31;
    const int w    = t >> 5;
    const int b    = blockIdx.x >> 6;        // batch
    const int c0   = (blockIdx.x & 63) * CPB;

    // clear histograms
    for (int i = t; i < CPB * HSTRIDE; i += 256) hist[i] = 0;
    __syncthreads();

    // ---- load + transpose into smem + fused level-0 histogram --------------
    {
        const int q   = t & 1;               // which half of the 8 channels
        const int hw0 = t >> 1;              // 0..127
        const float4* src = reinterpret_cast<const float4*>(
            x + (size_t)b * HWN * NCH + c0 + q * 4);
        const int chb = q * 4;
#pragma unroll 5
        for (int i = 0; i < 25; i++) {
            int hw = hw0 + i * 128;
            if (hw < HWN) {
                float4 v = src[(size_t)hw * (NCH / 4)];
                unsigned k0 = f2key(__float_as_uint(v.x));
                unsigned k1 = f2key(__float_as_uint(v.y));
                unsigned k2 = f2key(__float_as_uint(v.z));
                unsigned k3 = f2key(__float_as_uint(v.w));
                keys[(chb + 0) * STRIDE + hw] = k0;
                keys[(chb + 1) * STRIDE + hw] = k1;
                keys[(chb + 2) * STRIDE + hw] = k2;
                keys[(chb + 3) * STRIDE + hw] = k3;
                atomicAdd(&hist[(chb + 0) * HSTRIDE + (k0 >> 24)], 1u);
                atomicAdd(&hist[(chb + 1) * HSTRIDE + (k1 >> 24)], 1u);
                atomicAdd(&hist[(chb + 2) * HSTRIDE + (k2 >> 24)], 1u);
                atomicAdd(&hist[(chb + 3) * HSTRIDE + (k3 >> 24)], 1u);
            }
        }
    }
    __syncthreads();

    // ---- per-warp (= per-channel) selection --------------------------------
    const uint4* row4 = reinterpret_cast<const uint4*>(keys + w * STRIDE);
    unsigned* h = hist + w * HSTRIDE;

    // level-0 walks: top end rank KSEL, bottom end = (n - k + 1)-th from largest
    int2 st = walk(h, 0, lane, KSEL);
    int2 sb = walk(h, 0, lane, HWN - KSEL + 1);
    unsigned pfxT = (unsigned)st.x << 24;
    unsigned pfxB = (unsigned)sb.x << 24;
    int rT = st.y, rB = sb.y;

    // refinement levels 1..3 (one scan each serves both ends: low16=top, high16=bottom)
#pragma unroll 1
    for (int lvl = 1; lvl <= 3; lvl++) {
        const int shift = 8 * (3 - lvl);                     // 16, 8, 0
        const unsigned pmask = 0xFFFFFFFFu << (shift + 8);   // matched prefix bits
        __syncwarp();
        for (int i = lane; i < 256; i += 32) h[i] = 0;
        __syncwarp();
#pragma unroll 1
        for (int i = 0; i < 25; i++) {
            int col = i * 32 + lane;
            bool valid = col < NQ;
            uint4 kv = valid ? row4[col] : make_uint4(0u, 0u, 0u, 0u);
            unsigned ks[4] = {kv.x, kv.y, kv.z, kv.w};
#pragma unroll
            for (int e = 0; e < 4; e++) {
                unsigned kk = ks[e];
                unsigned bt = (valid && (kk & pmask) == pfxT)
                                  ? ((kk >> shift) & 0xFFu) : (unsigned)(256 + lane);
                unsigned m1 = __match_any_sync(FULLMASK, bt);
                if (bt < 256u && lane == __ffs((int)m1) - 1)
                    atomicAdd(&h[bt], (unsigned)__popc(m1));
                unsigned bb = (valid && (kk & pmask) == pfxB)
                                  ? ((kk >> shift) & 0xFFu) : (unsigned)(256 + lane);
                unsigned m2 = __match_any_sync(FULLMASK, bb);
                if (bb < 256u && lane == __ffs((int)m2) - 1)
                    atomicAdd(&h[bb], ((unsigned)__popc(m2)) << 16);
            }
        }
        __syncwarp();
        int2 wt = walk(h, 0,  lane, rT);
        int2 wb = walk(h, 16, lane, rB);
        pfxT |= (unsigned)wt.x << shift;
        pfxB |= (unsigned)wb.x << shift;
        rT = wt.y; rB = wb.y;
    }

    // pfxT / pfxB now hold the exact 32-bit keys of the k-th largest / k-th smallest
    const unsigned Tmax = pfxT, Tmin = pfxB;

    // ---- stats pass: strict counts + sums for both ends --------------------
    int cg = 0, cl = 0;
    float sg = 0.f, sl = 0.f;
#pragma unroll 1
    for (int i = 0; i < 25; i++) {
        int col = i * 32 + lane;
        if (col < NQ) {
            uint4 kv = row4[col];
            unsigned ks[4] = {kv.x, kv.y, kv.z, kv.w};
#pragma unroll
            for (int e = 0; e < 4; e++) {
                unsigned kk = ks[e];
                if (kk > Tmax) { cg++; sg += key2f(kk); }
                if (kk < Tmin) { cl++; sl += key2f(kk); }
            }
        }
    }
    cg = wredi(cg); sg = wredf(sg);
    cl = wredi(cl); sl = wredf(sl);

    if (lane == 0) {
        float vT = key2f(Tmax), vB = key2f(Tmin);
        float xmax = (sg + (float)(KSEL - cg) * vT) * (1.0f / (float)KSEL);
        float xmin = (sl + (float)(KSEL - cl) * vB) * (ALPHA / (float)KSEL);
        out[b * NCH + c0 + w] = 0.5f * (xmax + xmin);
    }
}

extern "C" void kernel_launch(void* const* d_in, const int* in_sizes, int n_in,
                              void* d_out, int out_size)
{
    const float* x = (const float*)d_in[0];
    float* out = (float*)d_out;
    cudaFuncSetAttribute(wildcat_kernel,
                         cudaFuncAttributeMaxDynamicSharedMemorySize,
                         SMEM_WORDS * (int)sizeof(unsigned));
    wildcat_kernel<<<NBATCH * (NCH / CPB), 256, SMEM_WORDS * sizeof(unsigned)>>>(x, out);
}

// round 5
// speedup vs baseline: 11.3066x; 11.3066x over previous
#include <cuda_runtime.h>
#include <cuda_bf16.h>
#include <stdint.h>

#define FULLMASK 0xFFFFFFFFu

constexpr int HWN     = 3136;   // 56*56
constexpr int NCH     = 512;
constexpr int NBATCH  = 32;
constexpr int CPB     = 8;      // channels per block (1 per warp)
constexpr int KSEL    = 627;    // round(0.2*3136)
constexpr int STRIDE  = 3140;   // smem row stride (u32), 16B aligned
constexpr int NQ      = HWN / 4;        // 784 uint4 per row
constexpr int HSTRIDE = 264;    // histogram row stride
constexpr int SMEM_WORDS = CPB * STRIDE + CPB * HSTRIDE;
constexpr float ALPHA = 0.7f;

// monotone float -> u32 key (ascending float == ascending unsigned)
__device__ __forceinline__ unsigned f2key(unsigned b) {
    return (b & 0x80000000u) ? ~b : (b | 0x80000000u);
}
__device__ __forceinline__ float key2f(unsigned u) {
    return __uint_as_float((u & 0x80000000u) ? (u & 0x7FFFFFFFu) : ~u);
}

__device__ __forceinline__ int wredi(int v) {
#pragma unroll
    for (int d = 16; d; d >>= 1) v += __shfl_xor_sync(FULLMASK, v, d);
    return v;
}
__device__ __forceinline__ float wredf(float v) {
#pragma unroll
    for (int d = 16; d; d >>= 1) v += __shfl_xor_sync(FULLMASK, v, d);
    return v;
}

// Warp-parallel rank walk over a 256-bin histogram, rank r is 1-based FROM THE
// LARGEST bin. Counts are ((hist[i] >> shift) & 0xFFFF). Returns (bin, rankInBin).
__device__ __forceinline__ int2 walk(const unsigned* hist, int shift, int lane, int r)
{
    unsigned c[8];
    int s = 0;
#pragma unroll
    for (int j = 0; j < 8; j++) {
        c[j] = (hist[lane * 8 + j] >> shift) & 0xFFFFu;
        s += (int)c[j];
    }
    // inclusive suffix sum across lanes (sum over lanes >= lane)
    int incl = s;
#pragma unroll
    for (int d = 1; d < 32; d <<= 1) {
        int v = __shfl_down_sync(FULLMASK, incl, d);
        if (lane + d < 32) incl += v;
    }
    int hi = incl - s;                      // count in bins above this lane's 8
    bool sel = (hi < r) && (r <= hi + s);
    unsigned bal = __ballot_sync(FULLMASK, sel);
    int L = __ffs((int)bal) - 1;
    int bin = -1, rr = 0;
    if (lane == L) {
        int rloc = r - hi;
        int cum = 0;
#pragma unroll
        for (int j = 7; j >= 0; j--) {      // from largest bin within lane
            if (bin < 0 && rloc <= cum + (int)c[j]) { bin = j; rr = rloc - cum; }
            cum += (int)c[j];
        }
        bin += lane * 8;
    }
    bin = __shfl_sync(FULLMASK, bin, L);
    rr  = __shfl_sync(FULLMASK, rr,  L);
    return make_int2(bin, rr);
}

extern __shared__ unsigned smem[];

__global__ void __launch_bounds__(256, 2)
wildcat_kernel(const float* __restrict__ x, float* __restrict__ out)
{
    unsigned* keys = smem;                   // CPB * STRIDE
    unsigned* hist = smem + CPB * STRIDE;    // CPB * HSTRIDE

    const int t    = threadIdx.x;
    const int lane = t & 31;
    const int w    = t >> 5;
    const int b    = blockIdx.x >> 6;        // batch
    const int c0   = (blockIdx.x & 63) * CPB;

    // ---- pure streaming load + transpose into smem -------------------------
    {
        const int q   = t & 1;               // which half of the 8 channels
        const int hw0 = t >> 1;              // 0..127
        const float4* src = reinterpret_cast<const float4*>(
            x + (size_t)b * HWN * NCH + c0 + q * 4);
        const int chb = q * 4;
#pragma unroll 5
        for (int i = 0; i < 25; i++) {
            int hw = hw0 + i * 128;
            if (hw < HWN) {
                float4 v = src[(size_t)hw * (NCH / 4)];
                keys[(chb + 0) * STRIDE + hw] = f2key(__float_as_uint(v.x));
                keys[(chb + 1) * STRIDE + hw] = f2key(__float_as_uint(v.y));
                keys[(chb + 2) * STRIDE + hw] = f2key(__float_as_uint(v.z));
                keys[(chb + 3) * STRIDE + hw] = f2key(__float_as_uint(v.w));
            }
        }
    }
    __syncthreads();

    // ---- per-warp (= per-channel) selection --------------------------------
    const uint4* row4 = reinterpret_cast<const uint4*>(keys + w * STRIDE);
    unsigned* h = hist + w * HSTRIDE;

    // level-0 scan: match-aggregated histogram (bins are concentrated here,
    // raw atomics would serialize ~16-way on the popular exponent bin)
    for (int i = lane; i < 256; i += 32) h[i] = 0;
    __syncwarp();
#pragma unroll 1
    for (int i = 0; i < 25; i++) {
        int col = i * 32 + lane;
        bool valid = col < NQ;
        uint4 kv = valid ? row4[col] : make_uint4(0u, 0u, 0u, 0u);
        unsigned ks[4] = {kv.x, kv.y, kv.z, kv.w};
#pragma unroll
        for (int e = 0; e < 4; e++) {
            unsigned bin = valid ? (ks[e] >> 24) : (0x100u + (unsigned)lane);
            unsigned m = __match_any_sync(FULLMASK, bin);
            if (valid && lane == (__ffs((int)m) - 1))
                atomicAdd(&h[bin], (unsigned)__popc(m));
        }
    }
    __syncwarp();

    // level-0 walks: top end rank KSEL, bottom end = (n - k + 1)-th from largest
    int2 st = walk(h, 0, lane, KSEL);
    int2 sb = walk(h, 0, lane, HWN - KSEL + 1);
    unsigned pfxT = (unsigned)st.x << 24;
    unsigned pfxB = (unsigned)sb.x << 24;
    int rT = st.y, rB = sb.y;

    // refinement levels 1..3: participation is sparse and next-byte bins are
    // mantissa bits (near-uniform) -> predicated raw atomics, no match needed.
    // One scan serves both ends (low16 = top counts, high16 = bottom counts).
#pragma unroll 1
    for (int lvl = 1; lvl <= 3; lvl++) {
        const int shift = 8 * (3 - lvl);                     // 16, 8, 0
        const unsigned pmask = 0xFFFFFFFFu << (shift + 8);   // matched prefix bits
        __syncwarp();
        for (int i = lane; i < 256; i += 32) h[i] = 0;
        __syncwarp();
#pragma unroll 1
        for (int i = 0; i < 25; i++) {
            int col = i * 32 + lane;
            bool valid = col < NQ;
            uint4 kv = valid ? row4[col] : make_uint4(0u, 0u, 0u, 0u);
            unsigned ks[4] = {kv.x, kv.y, kv.z, kv.w};
#pragma unroll
            for (int e = 0; e < 4; e++) {
                unsigned kk = ks[e];
                if (valid && (kk & pmask) == pfxT)
                    atomicAdd(&h[(kk >> shift) & 0xFFu], 1u);
                if (valid && (kk & pmask) == pfxB)
                    atomicAdd(&h[(kk >> shift) & 0xFFu], 0x10000u);
            }
        }
        __syncwarp();
        int2 wt = walk(h, 0,  lane, rT);
        int2 wb = walk(h, 16, lane, rB);
        pfxT |= (unsigned)wt.x << shift;
        pfxB |= (unsigned)wb.x << shift;
        rT = wt.y; rB = wb.y;
    }

    // pfxT / pfxB now hold the exact 32-bit keys of the k-th largest / k-th smallest
    const unsigned Tmax = pfxT, Tmin = pfxB;

    // ---- stats pass: strict counts + sums for both ends --------------------
    int cg = 0, cl = 0;
    float sg = 0.f, sl = 0.f;
#pragma unroll 1
    for (int i = 0; i < 25; i++) {
        int col = i * 32 + lane;
        if (col < NQ) {
            uint4 kv = row4[col];
            unsigned ks[4] = {kv.x, kv.y, kv.z, kv.w};
#pragma unroll
            for (int e = 0; e < 4; e++) {
                unsigned kk = ks[e];
                if (kk > Tmax) { cg++; sg += key2f(kk); }
                if (kk < Tmin) { cl++; sl += key2f(kk); }
            }
        }
    }
    cg = wredi(cg); sg = wredf(sg);
    cl = wredi(cl); sl = wredf(sl);

    if (lane == 0) {
        float vT = key2f(Tmax), vB = key2f(Tmin);
        float xmax = (sg + (float)(KSEL - cg) * vT) * (1.0f / (float)KSEL);
        float xmin = (sl + (float)(KSEL - cl) * vB) * (ALPHA / (float)KSEL);
        out[b * NCH + c0 + w] = 0.5f * (xmax + xmin);
    }
}

extern "C" void kernel_launch(void* const* d_in, const int* in_sizes, int n_in,
                              void* d_out, int out_size)
{
    const float* x = (const float*)d_in[0];
    float* out = (float*)d_out;
    cudaFuncSetAttribute(wildcat_kernel,
                         cudaFuncAttributeMaxDynamicSharedMemorySize,
                         SMEM_WORDS * (int)sizeof(unsigned));
    wildcat_kernel<<<NBATCH * (NCH / CPB), 256, SMEM_WORDS * sizeof(unsigned)>>>(x, out);
}

// round 6
// speedup vs baseline: 12.8145x; 1.1334x over previous
#include <cuda_runtime.h>
#include <cuda_bf16.h>
#include <stdint.h>

#define FULLMASK 0xFFFFFFFFu

constexpr int HWN     = 3136;   // 56*56
constexpr int NCH     = 512;
constexpr int NBATCH  = 32;
constexpr int CPB     = 8;      // channels per block (2 warps per channel)
constexpr int KSEL    = 627;    // round(0.2*3136)
constexpr int STRIDE  = 3140;   // smem row stride (u32), 16B aligned
constexpr int NQ      = HWN / 4;        // 784 uint4 per row
constexpr int HQ      = NQ / 2;         // 392 uint4 per warp (half row)
constexpr int SCAN_IT = (HQ + 31) / 32; // 13
constexpr int HSTRIDE = 264;    // histogram row stride (256 bins + 8 spare accum words)
constexpr int SMEM_WORDS = CPB * STRIDE + CPB * HSTRIDE;
constexpr float ALPHA = 0.7f;

// monotone float -> u32 key (ascending float == ascending unsigned)
__device__ __forceinline__ unsigned f2key(unsigned b) {
    return (b & 0x80000000u) ? ~b : (b | 0x80000000u);
}
__device__ __forceinline__ float key2f(unsigned u) {
    return __uint_as_float((u & 0x80000000u) ? (u & 0x7FFFFFFFu) : ~u);
}

__device__ __forceinline__ int wredi(int v) {
#pragma unroll
    for (int d = 16; d; d >>= 1) v += __shfl_xor_sync(FULLMASK, v, d);
    return v;
}
__device__ __forceinline__ float wredf(float v) {
#pragma unroll
    for (int d = 16; d; d >>= 1) v += __shfl_xor_sync(FULLMASK, v, d);
    return v;
}

// Warp-parallel rank walk over a 256-bin histogram, rank r is 1-based FROM THE
// LARGEST bin. Counts are ((hist[i] >> shift) & 0xFFFF). Returns (bin, rankInBin).
// Integer-only: warps of a pair run it redundantly and get identical results.
__device__ __forceinline__ int2 walk(const unsigned* hist, int shift, int lane, int r)
{
    unsigned c[8];
    int s = 0;
#pragma unroll
    for (int j = 0; j < 8; j++) {
        c[j] = (hist[lane * 8 + j] >> shift) & 0xFFFFu;
        s += (int)c[j];
    }
    // inclusive suffix sum across lanes (sum over lanes >= lane)
    int incl = s;
#pragma unroll
    for (int d = 1; d < 32; d <<= 1) {
        int v = __shfl_down_sync(FULLMASK, incl, d);
        if (lane + d < 32) incl += v;
    }
    int hi = incl - s;                      // count in bins above this lane's 8
    bool sel = (hi < r) && (r <= hi + s);
    unsigned bal = __ballot_sync(FULLMASK, sel);
    int L = __ffs((int)bal) - 1;
    int bin = -1, rr = 0;
    if (lane == L) {
        int rloc = r - hi;
        int cum = 0;
#pragma unroll
        for (int j = 7; j >= 0; j--) {      // from largest bin within lane
            if (bin < 0 && rloc <= cum + (int)c[j]) { bin = j; rr = rloc - cum; }
            cum += (int)c[j];
        }
        bin += lane * 8;
    }
    bin = __shfl_sync(FULLMASK, bin, L);
    rr  = __shfl_sync(FULLMASK, rr,  L);
    return make_int2(bin, rr);
}

extern __shared__ unsigned smem[];

__global__ void __launch_bounds__(512, 2)
wildcat_kernel(const float* __restrict__ x, float* __restrict__ out)
{
    unsigned* keys = smem;                   // CPB * STRIDE
    unsigned* hist = smem + CPB * STRIDE;    // CPB * HSTRIDE

    const int t    = threadIdx.x;
    const int lane = t & 31;
    const int warp = t >> 5;                 // 0..15
    const int w    = warp >> 1;              // channel 0..7
    const int hf   = warp & 1;               // which half of the spatial row
    const int b    = blockIdx.x >> 6;        // batch
    const int c0   = (blockIdx.x & 63) * CPB;

    // zero all histograms + accumulator slots
    for (int i = t; i < CPB * HSTRIDE; i += 512) hist[i] = 0;

    // ---- pure streaming load + transpose into smem -------------------------
    {
        const int q   = t & 1;               // which float4 of the 8 channels
        const int hw0 = t >> 1;              // 0..255
        const float4* src = reinterpret_cast<const float4*>(
            x + (size_t)b * HWN * NCH + c0 + q * 4);
        const int chb = q * 4;
#pragma unroll
        for (int i = 0; i < 13; i++) {
            int hw = hw0 + i * 256;
            if (hw < HWN) {
                float4 v = src[(size_t)hw * (NCH / 4)];
                keys[(chb + 0) * STRIDE + hw] = f2key(__float_as_uint(v.x));
                keys[(chb + 1) * STRIDE + hw] = f2key(__float_as_uint(v.y));
                keys[(chb + 2) * STRIDE + hw] = f2key(__float_as_uint(v.z));
                keys[(chb + 3) * STRIDE + hw] = f2key(__float_as_uint(v.w));
            }
        }
    }
    __syncthreads();

    // ---- per-warp-pair (= per-channel) selection ---------------------------
    const uint4* row4 = reinterpret_cast<const uint4*>(keys + w * STRIDE);
    unsigned* hh = hist + w * HSTRIDE;
    const int base = hf * HQ;                // this warp's half of the row

    // level-0 scan: match-aggregated histogram (bins concentrated; raw atomics
    // would serialize on the popular exponent bin)
#pragma unroll 1
    for (int i = 0; i < SCAN_IT; i++) {
        int idx = i * 32 + lane;
        bool valid = idx < HQ;
        uint4 kv = valid ? row4[base + idx] : make_uint4(0u, 0u, 0u, 0u);
        unsigned ks[4] = {kv.x, kv.y, kv.z, kv.w};
#pragma unroll
        for (int e = 0; e < 4; e++) {
            unsigned bin = valid ? (ks[e] >> 24) : (0x100u + (unsigned)lane);
            unsigned m = __match_any_sync(FULLMASK, bin);
            if (valid && lane == (__ffs((int)m) - 1))
                atomicAdd(&hh[bin], (unsigned)__popc(m));
        }
    }
    __syncthreads();

    // level-0 walks: top end rank KSEL, bottom end = (n - k + 1)-th from largest
    int2 st = walk(hh, 0, lane, KSEL);
    int2 sb = walk(hh, 0, lane, HWN - KSEL + 1);
    unsigned pfxT = (unsigned)st.x << 24;
    unsigned pfxB = (unsigned)sb.x << 24;
    int rT = st.y, rB = sb.y;

    // refinement levels 1..3: sparse participation, near-uniform next-byte bins
    // -> predicated raw atomics. One scan serves both ends (low16=top, high16=bottom).
#pragma unroll 1
    for (int lvl = 1; lvl <= 3; lvl++) {
        const int shift = 8 * (3 - lvl);                     // 16, 8, 0
        const unsigned pmask = 0xFFFFFFFFu << (shift + 8);   // matched prefix bits
        __syncthreads();                                      // pair done reading hist
        for (int i = lane; i < HSTRIDE; i += 32) hh[i] = 0;  // both warps (benign race)
        __syncthreads();
#pragma unroll 1
        for (int i = 0; i < SCAN_IT; i++) {
            int idx = i * 32 + lane;
            bool valid = idx < HQ;
            uint4 kv = valid ? row4[base + idx] : make_uint4(0u, 0u, 0u, 0u);
            unsigned ks[4] = {kv.x, kv.y, kv.z, kv.w};
#pragma unroll
            for (int e = 0; e < 4; e++) {
                unsigned kk = ks[e];
                if (valid && (kk & pmask) == pfxT)
                    atomicAdd(&hh[(kk >> shift) & 0xFFu], 1u);
                if (valid && (kk & pmask) == pfxB)
                    atomicAdd(&hh[(kk >> shift) & 0xFFu], 0x10000u);
            }
        }
        __syncthreads();
        int2 wt = walk(hh, 0,  lane, rT);
        int2 wb = walk(hh, 16, lane, rB);
        pfxT |= (unsigned)wt.x << shift;
        pfxB |= (unsigned)wb.x << shift;
        rT = wt.y; rB = wb.y;
    }

    // pfxT / pfxB are the exact keys of the k-th largest / k-th smallest
    const unsigned Tmax = pfxT, Tmin = pfxB;

    // ---- stats pass: strict counts + sums for both ends (per half) ---------
    int cg = 0, cl = 0;
    float sg = 0.f, sl = 0.f;
#pragma unroll 1
    for (int i = 0; i < SCAN_IT; i++) {
        int idx = i * 32 + lane;
        if (idx < HQ) {
            uint4 kv = row4[base + idx];
            unsigned ks[4] = {kv.x, kv.y, kv.z, kv.w};
#pragma unroll
            for (int e = 0; e < 4; e++) {
                unsigned kk = ks[e];
                if (kk > Tmax) { cg++; sg += key2f(kk); }
                if (kk < Tmin) { cl++; sl += key2f(kk); }
            }
        }
    }
    cg = wredi(cg); sg = wredf(sg);
    cl = wredi(cl); sl = wredf(sl);

    // combine the two halves through spare accumulator slots (zeroed at L3)
    unsigned* accU = hh + 256;
    if (lane == 0) {
        atomicAdd(&accU[0], (unsigned)cg);
        atomicAdd(reinterpret_cast<float*>(&accU[1]), sg);
        atomicAdd(&accU[2], (unsigned)cl);
        atomicAdd(reinterpret_cast<float*>(&accU[3]), sl);
    }
    __syncthreads();

    if (hf == 0 && lane == 0) {
        int   Cg = (int)accU[0];
        float Sg = reinterpret_cast<float*>(accU)[1];
        int   Cl = (int)accU[2];
        float Sl = reinterpret_cast<float*>(accU)[3];
        float vT = key2f(Tmax), vB = key2f(Tmin);
        float xmax = (Sg + (float)(KSEL - Cg) * vT) * (1.0f / (float)KSEL);
        float xmin = (Sl + (float)(KSEL - Cl) * vB) * (ALPHA / (float)KSEL);
        out[b * NCH + c0 + w] = 0.5f * (xmax + xmin);
    }
}

extern "C" void kernel_launch(void* const* d_in, const int* in_sizes, int n_in,
                              void* d_out, int out_size)
{
    const float* x = (const float*)d_in[0];
    float* out = (float*)d_out;
    cudaFuncSetAttribute(wildcat_kernel,
                         cudaFuncAttributeMaxDynamicSharedMemorySize,
                         SMEM_WORDS * (int)sizeof(unsigned));
    wildcat_kernel<<<NBATCH * (NCH / CPB), 512, SMEM_WORDS * sizeof(unsigned)>>>(x, out);
}

// round 7
// speedup vs baseline: 14.2038x; 1.1084x over previous
#include <cuda_runtime.h>
#include <cuda_bf16.h>
#include <stdint.h>

#define FULLMASK 0xFFFFFFFFu

constexpr int HWN     = 3136;   // 56*56
constexpr int NCH     = 512;
constexpr int NBATCH  = 32;
constexpr int CPB     = 8;      // channels per block (2 warps per channel)
constexpr int KSEL    = 627;    // round(0.2*3136)
constexpr int STRIDE  = 3140;   // smem row stride (u32), 16B aligned
constexpr int NQ      = HWN / 4;        // 784 uint4 per row
constexpr int HQ      = NQ / 2;         // 392 uint4 per warp half
constexpr int HELEM   = HQ * 4;         // 1568 elements per warp half
constexpr int SCAN_IT = (HQ + 31) / 32; // 13
constexpr int HSTRIDE = 264;    // 256 bins + 8 spare accumulator words
constexpr int SMEM_WORDS = CPB * STRIDE + CPB * HSTRIDE;
constexpr float ALPHA = 0.7f;

// monotone float -> u32 key (ascending float == ascending unsigned)
__device__ __forceinline__ unsigned f2key(unsigned b) {
    return (b & 0x80000000u) ? ~b : (b | 0x80000000u);
}
__device__ __forceinline__ float key2f(unsigned u) {
    return __uint_as_float((u & 0x80000000u) ? (u & 0x7FFFFFFFu) : ~u);
}

__device__ __forceinline__ int wredi(int v) {
#pragma unroll
    for (int d = 16; d; d >>= 1) v += __shfl_xor_sync(FULLMASK, v, d);
    return v;
}
__device__ __forceinline__ float wredf(float v) {
#pragma unroll
    for (int d = 16; d; d >>= 1) v += __shfl_xor_sync(FULLMASK, v, d);
    return v;
}

// Warp-parallel rank walk over a 256-bin histogram, rank r 1-based FROM THE
// LARGEST bin. Counts are ((hist[i] >> shift) & 0xFFFF). Returns (bin, rankInBin).
__device__ __forceinline__ int2 walk(const unsigned* hist, int shift, int lane, int r)
{
    unsigned c[8];
    int s = 0;
#pragma unroll
    for (int j = 0; j < 8; j++) {
        c[j] = (hist[lane * 8 + j] >> shift) & 0xFFFFu;
        s += (int)c[j];
    }
    int incl = s;                           // suffix-sum over lanes >= lane
#pragma unroll
    for (int d = 1; d < 32; d <<= 1) {
        int v = __shfl_down_sync(FULLMASK, incl, d);
        if (lane + d < 32) incl += v;
    }
    int hi = incl - s;
    bool sel = (hi < r) && (r <= hi + s);
    unsigned bal = __ballot_sync(FULLMASK, sel);
    int L = __ffs((int)bal) - 1;
    int bin = -1, rr = 0;
    if (lane == L) {
        int rloc = r - hi, cum = 0;
#pragma unroll
        for (int j = 7; j >= 0; j--) {
            if (bin < 0 && rloc <= cum + (int)c[j]) { bin = j; rr = rloc - cum; }
            cum += (int)c[j];
        }
        bin += lane * 8;
    }
    bin = __shfl_sync(FULLMASK, bin, L);
    rr  = __shfl_sync(FULLMASK, rr,  L);
    return make_int2(bin, rr);
}

extern __shared__ unsigned smem[];

__global__ void __launch_bounds__(512, 2)
wildcat_kernel(const float* __restrict__ x, float* __restrict__ out)
{
    unsigned* keys = smem;                   // CPB * STRIDE
    unsigned* hist = smem + CPB * STRIDE;    // CPB * HSTRIDE

    const int t    = threadIdx.x;
    const int lane = t & 31;
    const int warp = t >> 5;                 // 0..15
    const int w    = warp >> 1;              // channel 0..7
    const int hf   = warp & 1;               // which half of the spatial row
    const int b    = blockIdx.x >> 6;        // batch
    const int c0   = (blockIdx.x & 63) * CPB;

    for (int i = t; i < CPB * HSTRIDE; i += 512) hist[i] = 0;
    __syncthreads();

    // ---- load + transpose + FUSED level-0 histogram ------------------------
    // Match keys carry the channel so lanes of different channels never merge;
    // aggregated atomics (1 per distinct (ch,bin) per round) hide under LDG latency.
    {
        const int q   = t & 1;               // which float4 of the 8 channels
        const int hw0 = t >> 1;              // 0..255
        const float4* src = reinterpret_cast<const float4*>(
            x + (size_t)b * HWN * NCH + c0 + q * 4);
        const int chb = q * 4;
#pragma unroll 4
        for (int i = 0; i < 13; i++) {
            int hw = hw0 + i * 256;
            bool valid = hw < HWN;
            unsigned k[4] = {0u, 0u, 0u, 0u};
            if (valid) {
                float4 v = src[(size_t)hw * (NCH / 4)];
                k[0] = f2key(__float_as_uint(v.x));
                k[1] = f2key(__float_as_uint(v.y));
                k[2] = f2key(__float_as_uint(v.z));
                k[3] = f2key(__float_as_uint(v.w));
                keys[(chb + 0) * STRIDE + hw] = k[0];
                keys[(chb + 1) * STRIDE + hw] = k[1];
                keys[(chb + 2) * STRIDE + hw] = k[2];
                keys[(chb + 3) * STRIDE + hw] = k[3];
            }
#pragma unroll
            for (int e = 0; e < 4; e++) {
                unsigned bin = k[e] >> 24;
                unsigned mk  = valid ? (((unsigned)(chb + e) << 8) | bin)
                                     : (0x4000u + (unsigned)lane);
                unsigned m = __match_any_sync(FULLMASK, mk);
                if (valid && lane == (__ffs((int)m) - 1))
                    atomicAdd(&hist[(chb + e) * HSTRIDE + bin], (unsigned)__popc(m));
            }
        }
    }
    __syncthreads();

    // ---- per-channel selection ---------------------------------------------
    unsigned* rowE = keys + w * STRIDE;       // element view of this channel row
    const uint4* row4 = reinterpret_cast<const uint4*>(rowE);
    unsigned* hh = hist + w * HSTRIDE;
    const int qBase = hf * HQ;                // uint4 base of own half
    const int eBase = hf * HELEM;             // element base of own half

    // L0 walks: top rank KSEL, bottom rank n-k+1 (both ends, from largest)
    int2 st = walk(hh, 0, lane, KSEL);
    int2 sb = walk(hh, 0, lane, HWN - KSEL + 1);
    const int selT = st.x, selB = sb.x;
    int rT = st.y, rB = sb.y;
    unsigned pfxT = (unsigned)selT << 24;
    unsigned pfxB = (unsigned)selB << 24;

    __syncthreads();
    for (int i = lane; i < 256; i += 32) hh[i] = 0;
    __syncthreads();

    // ---- L1: single full scan: compact candidates in place + partial stats -
    int cg = 0, cl = 0;
    float sg = 0.f, sl = 0.f;
    unsigned cnt = 0;                          // compacted elements (warp-uniform)
#pragma unroll 1
    for (int i = 0; i < SCAN_IT; i++) {
        int idx = i * 32 + lane;
        bool valid = idx < HQ;
        uint4 kv = valid ? row4[qBase + idx] : make_uint4(0u, 0u, 0u, 0u);
        unsigned ks[4] = {kv.x, kv.y, kv.z, kv.w};
#pragma unroll
        for (int e = 0; e < 4; e++) {
            unsigned kk = ks[e];
            int bin = (int)(kk >> 24);
            bool isT = valid && (bin == selT);
            bool isB = valid && (bin == selB);
            if (valid && bin > selT) { cg++; sg += key2f(kk); }
            if (valid && bin < selB) { cl++; sl += key2f(kk); }
            unsigned add = (isT ? 1u : 0u) + (isB ? 0x10000u : 0u);
            if (add) atomicAdd(&hh[(kk >> 16) & 0xFFu], add);
            bool cand = isT || isB;
            unsigned bal = __ballot_sync(FULLMASK, cand);
            if (cand) {
                unsigned pos = cnt + __popc(bal & ((1u << lane) - 1u));
                rowE[eBase + pos] = kk;        // pos < read frontier: in-warp safe
            }
            cnt += (unsigned)__popc(bal);
        }
    }
    __syncthreads();

    {   // L1 walks
        int2 wt = walk(hh, 0,  lane, rT);
        int2 wb = walk(hh, 16, lane, rB);
        pfxT |= (unsigned)wt.x << 16;
        pfxB |= (unsigned)wb.x << 16;
        rT = wt.y; rB = wb.y;
    }

    const int citers = (int)((cnt + 31u) >> 5);

    // ---- L2 over compact list ----------------------------------------------
    __syncthreads();
    for (int i = lane; i < 256; i += 32) hh[i] = 0;
    __syncthreads();
#pragma unroll 1
    for (int i = 0; i < citers; i++) {
        unsigned idx = (unsigned)(i * 32 + lane);
        if (idx < cnt) {
            unsigned kk = rowE[eBase + idx];
            unsigned hi16 = kk >> 16;
            unsigned add = ((hi16 == (pfxT >> 16)) ? 1u : 0u)
                         + ((hi16 == (pfxB >> 16)) ? 0x10000u : 0u);
            if (add) atomicAdd(&hh[(kk >> 8) & 0xFFu], add);
        }
    }
    __syncthreads();
    {
        int2 wt = walk(hh, 0,  lane, rT);
        int2 wb = walk(hh, 16, lane, rB);
        pfxT |= (unsigned)wt.x << 8;
        pfxB |= (unsigned)wb.x << 8;
        rT = wt.y; rB = wb.y;
    }

    // ---- L3 over compact list ----------------------------------------------
    __syncthreads();
    for (int i = lane; i < 256; i += 32) hh[i] = 0;
    __syncthreads();
#pragma unroll 1
    for (int i = 0; i < citers; i++) {
        unsigned idx = (unsigned)(i * 32 + lane);
        if (idx < cnt) {
            unsigned kk = rowE[eBase + idx];
            unsigned hi24 = kk >> 8;
            unsigned add = ((hi24 == (pfxT >> 8)) ? 1u : 0u)
                         + ((hi24 == (pfxB >> 8)) ? 0x10000u : 0u);
            if (add) atomicAdd(&hh[kk & 0xFFu], add);
        }
    }
    __syncthreads();
    {
        int2 wt = walk(hh, 0,  lane, rT);
        int2 wb = walk(hh, 16, lane, rB);
        pfxT |= (unsigned)wt.x;
        pfxB |= (unsigned)wb.x;
    }
    const unsigned Tmax = pfxT, Tmin = pfxB;   // exact k-th keys

    // ---- final stats over compact list (rest already accumulated at L1) ----
#pragma unroll 1
    for (int i = 0; i < citers; i++) {
        unsigned idx = (unsigned)(i * 32 + lane);
        if (idx < cnt) {
            unsigned kk = rowE[eBase + idx];
            if (kk > Tmax) { cg++; sg += key2f(kk); }
            if (kk < Tmin) { cl++; sl += key2f(kk); }
        }
    }
    cg = wredi(cg); sg = wredf(sg);
    cl = wredi(cl); sl = wredf(sl);

    // combine the two halves via spare accumulator words (zeroed at init only)
    unsigned* accU = hh + 256;
    if (lane == 0) {
        atomicAdd(&accU[0], (unsigned)cg);
        atomicAdd(reinterpret_cast<float*>(&accU[1]), sg);
        atomicAdd(&accU[2], (unsigned)cl);
        atomicAdd(reinterpret_cast<float*>(&accU[3]), sl);
    }
    __syncthreads();

    if (hf == 0 && lane == 0) {
        int   Cg = (int)accU[0];
        float Sg = reinterpret_cast<float*>(accU)[1];
        int   Cl = (int)accU[2];
        float Sl = reinterpret_cast<float*>(accU)[3];
        float vT = key2f(Tmax), vB = key2f(Tmin);
        float xmax = (Sg + (float)(KSEL - Cg) * vT) * (1.0f / (float)KSEL);
        float xmin = (Sl + (float)(KSEL - Cl) * vB) * (ALPHA / (float)KSEL);
        out[b * NCH + c0 + w] = 0.5f * (xmax + xmin);
    }
}

extern "C" void kernel_launch(void* const* d_in, const int* in_sizes, int n_in,
                              void* d_out, int out_size)
{
    const float* x = (const float*)d_in[0];
    float* out = (float*)d_out;
    cudaFuncSetAttribute(wildcat_kernel,
                         cudaFuncAttributeMaxDynamicSharedMemorySize,
                         SMEM_WORDS * (int)sizeof(unsigned));
    wildcat_kernel<<<NBATCH * (NCH / CPB), 512, SMEM_WORDS * sizeof(unsigned)>>>(x, out);
}

// round 8
// speedup vs baseline: 14.4996x; 1.0208x over previous
#include <cuda_runtime.h>
#include <cuda_bf16.h>
#include <stdint.h>

#define FULLMASK 0xFFFFFFFFu

constexpr int HWN     = 3136;   // 56*56
constexpr int NCH     = 512;
constexpr int NBATCH  = 32;
constexpr int CPB     = 4;      // channels per block (4 warps per channel)
constexpr int KSEL    = 627;    // round(0.2*3136)
constexpr int RBRANK  = HWN - KSEL + 1;  // bottom-end rank from largest
constexpr int STRIDE  = 3140;   // smem row stride (u32), 16B aligned
constexpr int NQ      = HWN / 4;        // 784 uint4 per row
constexpr int QQ      = NQ / 4;         // 196 uint4 per warp quarter
constexpr int QELEM   = QQ * 4;         // 784 elements per quarter
constexpr int SCAN_IT = (QQ + 31) / 32; // 7
constexpr int HSTRIDE = 264;    // 256 bins + 8 spare accumulator words
constexpr int SMEM_WORDS = CPB * STRIDE + CPB * HSTRIDE;
constexpr float ALPHA = 0.7f;

__device__ __forceinline__ float key2f(unsigned u) {
    return __uint_as_float((u & 0x80000000u) ? (u & 0x7FFFFFFFu) : ~u);
}
// branch-free monotone key from float bits: kk = b ^ ((b>>31)|0x80000000)
__device__ __forceinline__ unsigned mkey(unsigned b) {
    return b ^ ((unsigned)(((int)b) >> 31) | 0x80000000u);
}

__device__ __forceinline__ float wredf(float v) {
#pragma unroll
    for (int d = 16; d; d >>= 1) v += __shfl_xor_sync(FULLMASK, v, d);
    return v;
}

// Warp-parallel rank walk over a 256-bin histogram; rank r is 1-based FROM THE
// LARGEST bin. Counts are ((hist[i] >> shift) & 0xFFFF).
// Returns (bin, rankInBin, countOfBin). Integer-only => redundant-warp safe.
__device__ __forceinline__ int3 walk(const unsigned* hist, int shift, int lane, int r)
{
    unsigned c[8];
    int s = 0;
#pragma unroll
    for (int j = 0; j < 8; j++) {
        c[j] = (hist[lane * 8 + j] >> shift) & 0xFFFFu;
        s += (int)c[j];
    }
    int incl = s;                           // suffix-sum over lanes >= lane
#pragma unroll
    for (int d = 1; d < 32; d <<= 1) {
        int v = __shfl_down_sync(FULLMASK, incl, d);
        if (lane + d < 32) incl += v;
    }
    int hi = incl - s;
    bool sel = (hi < r) && (r <= hi + s);
    unsigned bal = __ballot_sync(FULLMASK, sel);
    int L = __ffs((int)bal) - 1;
    int bin = -1, rr = 0, cc = 0;
    if (lane == L) {
        int rloc = r - hi, cum = 0;
#pragma unroll
        for (int j = 7; j >= 0; j--) {
            if (bin < 0 && rloc <= cum + (int)c[j]) { bin = j; rr = rloc - cum; cc = (int)c[j]; }
            cum += (int)c[j];
        }
        bin += lane * 8;
    }
    bin = __shfl_sync(FULLMASK, bin, L);
    rr  = __shfl_sync(FULLMASK, rr,  L);
    cc  = __shfl_sync(FULLMASK, cc,  L);
    return make_int3(bin, rr, cc);
}

extern __shared__ unsigned smem[];

__global__ void __launch_bounds__(512, 3)
wildcat_kernel(const float* __restrict__ x, float* __restrict__ out)
{
    unsigned* vals = smem;                   // CPB * STRIDE  (raw float bits)
    unsigned* hist = smem + CPB * STRIDE;    // CPB * HSTRIDE

    const int t    = threadIdx.x;
    const int lane = t & 31;
    const int warp = t >> 5;                 // 0..15
    const int w    = warp >> 2;              // channel 0..3
    const int q    = warp & 3;               // quarter of the spatial row
    const int b    = blockIdx.x >> 7;        // batch
    const int c0   = (blockIdx.x & 127) * CPB;

    for (int i = t; i < CPB * HSTRIDE; i += 512) hist[i] = 0;
    __syncthreads();

    // ---- load + transpose (values) + FUSED level-0 histogram ----------------
    {
        const float4* src = reinterpret_cast<const float4*>(
            x + (size_t)b * HWN * NCH + c0);
#pragma unroll 2
        for (int i = 0; i < 7; i++) {
            int hw = t + i * 512;
            bool valid = hw < HWN;
            unsigned k[4] = {0u, 0u, 0u, 0u};
            if (valid) {
                float4 v = src[(size_t)hw * (NCH / 4)];
                k[0] = __float_as_uint(v.x);
                k[1] = __float_as_uint(v.y);
                k[2] = __float_as_uint(v.z);
                k[3] = __float_as_uint(v.w);
                vals[0 * STRIDE + hw] = k[0];
                vals[1 * STRIDE + hw] = k[1];
                vals[2 * STRIDE + hw] = k[2];
                vals[3 * STRIDE + hw] = k[3];
            }
#pragma unroll
            for (int e = 0; e < 4; e++) {
                unsigned bin = mkey(k[e]) >> 24;
                unsigned mk  = valid ? (((unsigned)e << 8) | bin)
                                     : (0x1000u + (unsigned)lane);
                unsigned m = __match_any_sync(FULLMASK, mk);
                if (valid && lane == (__ffs((int)m) - 1))
                    atomicAdd(&hist[e * HSTRIDE + bin], (unsigned)__popc(m));
            }
        }
    }
    __syncthreads();

    // ---- per-channel selection ---------------------------------------------
    unsigned* rowU = vals + w * STRIDE;
    const uint4* row4 = reinterpret_cast<const uint4*>(rowU);
    unsigned* hh = hist + w * HSTRIDE;
    const int qBase = q * QQ;
    const int eBase = q * QELEM;

    // L0 walks (redundant across the 4 warps of the channel — identical results)
    int3 st = walk(hh, 0, lane, KSEL);
    int3 sb = walk(hh, 0, lane, RBRANK);
    const int selT = st.x, selB = sb.x;
    int rT = st.y, rB = sb.y;
    unsigned pfxT = (unsigned)selT << 24;
    unsigned pfxB = (unsigned)selB << 24;

    __syncthreads();
    for (int i = lane; i < 256; i += 32) hh[i] = 0;   // redundant same-value writes
    __syncthreads();

    // ---- L1: single full scan: sure-sums + candidate compaction + hist -----
    float sg = 0.f, sl = 0.f;
    unsigned cnt = 0;                          // compacted count (warp-uniform)
#pragma unroll 1
    for (int i = 0; i < SCAN_IT; i++) {
        int idx = i * 32 + lane;
        bool valid = idx < QQ;
        uint4 kv = valid ? row4[qBase + idx] : make_uint4(0u, 0u, 0u, 0u);
        unsigned ks[4] = {kv.x, kv.y, kv.z, kv.w};
#pragma unroll
        for (int e = 0; e < 4; e++) {
            unsigned bb = ks[e];
            unsigned kk = mkey(bb);
            int bin = (int)(kk >> 24);
            float v = __uint_as_float(bb);
            if (valid && bin > selT) sg += v;
            if (valid && bin < selB) sl += v;
            unsigned add = (valid && bin == selT ? 1u : 0u)
                         + (valid && bin == selB ? 0x10000u : 0u);
            if (add) atomicAdd(&hh[(kk >> 16) & 0xFFu], add);
            unsigned bal = __ballot_sync(FULLMASK, add != 0u);
            if (add) {
                unsigned pos = cnt + __popc(bal & ((1u << lane) - 1u));
                rowU[eBase + pos] = bb;        // pos < read frontier: in-warp safe
            }
            cnt += (unsigned)__popc(bal);
        }
    }
    __syncthreads();

    {   // L1 walks
        int3 wt = walk(hh, 0,  lane, rT);
        int3 wb = walk(hh, 16, lane, rB);
        pfxT |= (unsigned)wt.x << 16;
        pfxB |= (unsigned)wb.x << 16;
        rT = wt.y; rB = wb.y;
    }
    const int citers = (int)((cnt + 31u) >> 5);

    // ---- L2 over compact list ----------------------------------------------
    __syncthreads();
    for (int i = lane; i < 256; i += 32) hh[i] = 0;
    __syncthreads();
#pragma unroll 1
    for (int i = 0; i < citers; i++) {
        unsigned idx = (unsigned)(i * 32 + lane);
        if (idx < cnt) {
            unsigned kk = mkey(rowU[eBase + idx]);
            unsigned hi16 = kk >> 16;
            unsigned add = ((hi16 == (pfxT >> 16)) ? 1u : 0u)
                         + ((hi16 == (pfxB >> 16)) ? 0x10000u : 0u);
            if (add) atomicAdd(&hh[(kk >> 8) & 0xFFu], add);
        }
    }
    __syncthreads();
    {
        int3 wt = walk(hh, 0,  lane, rT);
        int3 wb = walk(hh, 16, lane, rB);
        pfxT |= (unsigned)wt.x << 8;
        pfxB |= (unsigned)wb.x << 8;
        rT = wt.y; rB = wb.y;
    }

    // ---- L3 over compact list ----------------------------------------------
    __syncthreads();
    for (int i = lane; i < 256; i += 32) hh[i] = 0;
    __syncthreads();
#pragma unroll 1
    for (int i = 0; i < citers; i++) {
        unsigned idx = (unsigned)(i * 32 + lane);
        if (idx < cnt) {
            unsigned kk = mkey(rowU[eBase + idx]);
            unsigned hi24 = kk >> 8;
            unsigned add = ((hi24 == (pfxT >> 8)) ? 1u : 0u)
                         + ((hi24 == (pfxB >> 8)) ? 0x10000u : 0u);
            if (add) atomicAdd(&hh[kk & 0xFFu], add);
        }
    }
    __syncthreads();
    int rT3, rB3, eqB;
    {
        int3 wt = walk(hh, 0,  lane, rT);
        int3 wb = walk(hh, 16, lane, rB);
        pfxT |= (unsigned)wt.x;
        pfxB |= (unsigned)wb.x;
        rT3 = wt.y; rB3 = wb.y; eqB = wb.z;
    }
    const float vT = key2f(pfxT);
    const float vB = key2f(pfxB);

    // ---- stats tail over compact list (float compares, no key2f) -----------
#pragma unroll 1
    for (int i = 0; i < citers; i++) {
        unsigned idx = (unsigned)(i * 32 + lane);
        if (idx < cnt) {
            float v = __uint_as_float(rowU[eBase + idx]);
            if (v > vT) sg += v;
            if (v < vB) sl += v;
        }
    }
    sg = wredf(sg);
    sl = wredf(sl);

    // combine the 4 quarter-warps through spare accumulator words
    float* accF = reinterpret_cast<float*>(hh + 256);
    if (lane == 0) {
        atomicAdd(&accF[0], sg);
        atomicAdd(&accF[1], sl);
    }
    __syncthreads();

    if (q == 0 && lane == 0) {
        // counts come for free from the final walk ranks:
        int cg = KSEL - rT3;                       // strictly > vT
        int cGTb = RBRANK - rB3;                   // strictly > vB
        int cl = HWN - cGTb - eqB;                 // strictly < vB
        float Sg = accF[0], Sl = accF[1];
        float xmax = (Sg + (float)(KSEL - cg) * vT) * (1.0f / (float)KSEL);
        float xmin = (Sl + (float)(KSEL - cl) * vB) * (ALPHA / (float)KSEL);
        out[b * NCH + c0 + w] = 0.5f * (xmax + xmin);
    }
}

extern "C" void kernel_launch(void* const* d_in, const int* in_sizes, int n_in,
                              void* d_out, int out_size)
{
    const float* x = (const float*)d_in[0];
    float* out = (float*)d_out;
    cudaFuncSetAttribute(wildcat_kernel,
                         cudaFuncAttributeMaxDynamicSharedMemorySize,
                         SMEM_WORDS * (int)sizeof(unsigned));
    wildcat_kernel<<<NBATCH * (NCH / CPB), 512, SMEM_WORDS * sizeof(unsigned)>>>(x, out);
}

// round 9
// speedup vs baseline: 17.0956x; 1.1790x over previous
#include <cuda_runtime.h>
#include <cuda_bf16.h>
#include <stdint.h>

#define FULLMASK 0xFFFFFFFFu

constexpr int HWN     = 3136;   // 56*56
constexpr int NCH     = 512;
constexpr int NBATCH  = 32;
constexpr int CPB     = 4;      // channels per block (4 warps per channel)
constexpr int KSEL    = 627;    // round(0.2*3136)
constexpr int RBRANK  = HWN - KSEL + 1;  // bottom-end rank from largest
constexpr int STRIDE  = 3140;   // smem row stride (u32), 16B aligned
constexpr int NQ      = HWN / 4;        // 784 uint4 per row
constexpr int QQ      = NQ / 4;         // 196 uint4 per warp quarter
constexpr int QELEM   = QQ * 4;         // 784 elements per quarter
constexpr int SCAN_IT = (QQ + 31) / 32; // 7
constexpr int HSTR    = 528;    // 256 (bufA) + 256 (bufB) + 16 spare
constexpr int SMEM_WORDS = CPB * STRIDE + CPB * HSTR;
constexpr float ALPHA = 0.7f;

__device__ __forceinline__ float key2f(unsigned u) {
    return __uint_as_float((u & 0x80000000u) ? (u & 0x7FFFFFFFu) : ~u);
}
// branch-free monotone key from float bits
__device__ __forceinline__ unsigned mkey(unsigned b) {
    return b ^ ((unsigned)(((int)b) >> 31) | 0x80000000u);
}

__device__ __forceinline__ float wredf(float v) {
#pragma unroll
    for (int d = 16; d; d >>= 1) v += __shfl_xor_sync(FULLMASK, v, d);
    return v;
}

// Warp-parallel rank walk over a 256-bin histogram; rank r 1-based FROM THE
// LARGEST bin. Counts are ((hist[i] >> shift) & 0xFFFF).
// Returns (bin, rankInBin, countOfBin).
__device__ __forceinline__ int3 walk(const unsigned* hist, int shift, int lane, int r)
{
    unsigned c[8];
    int s = 0;
#pragma unroll
    for (int j = 0; j < 8; j++) {
        c[j] = (hist[lane * 8 + j] >> shift) & 0xFFFFu;
        s += (int)c[j];
    }
    int incl = s;                           // suffix-sum over lanes >= lane
#pragma unroll
    for (int d = 1; d < 32; d <<= 1) {
        int v = __shfl_down_sync(FULLMASK, incl, d);
        if (lane + d < 32) incl += v;
    }
    int hi = incl - s;
    bool sel = (hi < r) && (r <= hi + s);
    unsigned bal = __ballot_sync(FULLMASK, sel);
    int L = __ffs((int)bal) - 1;
    int bin = -1, rr = 0, cc = 0;
    if (lane == L) {
        int rloc = r - hi, cum = 0;
#pragma unroll
        for (int j = 7; j >= 0; j--) {
            if (bin < 0 && rloc <= cum + (int)c[j]) { bin = j; rr = rloc - cum; cc = (int)c[j]; }
            cum += (int)c[j];
        }
        bin += lane * 8;
    }
    bin = __shfl_sync(FULLMASK, bin, L);
    rr  = __shfl_sync(FULLMASK, rr,  L);
    cc  = __shfl_sync(FULLMASK, cc,  L);
    return make_int3(bin, rr, cc);
}

extern __shared__ unsigned smem[];

__global__ void __launch_bounds__(512, 3)
wildcat_kernel(const float* __restrict__ x, float* __restrict__ out)
{
    unsigned* vals = smem;                   // CPB * STRIDE (raw float bits)
    unsigned* hist = smem + CPB * STRIDE;    // CPB * HSTR

    const int t    = threadIdx.x;
    const int lane = t & 31;
    const int warp = t >> 5;                 // 0..15
    const int w    = warp >> 2;              // channel 0..3
    const int q    = warp & 3;               // quarter of the spatial row
    const int b    = blockIdx.x >> 7;        // batch
    const int c0   = (blockIdx.x & 127) * CPB;

    for (int i = t; i < CPB * HSTR; i += 512) hist[i] = 0;
    __syncthreads();

    // ---- load + transpose + FUSED level-0 histogram (into bufA) ------------
    {
        const float4* src = reinterpret_cast<const float4*>(
            x + (size_t)b * HWN * NCH + c0);
#pragma unroll 2
        for (int i = 0; i < 6; i++) {        // 6 full, unconditional iterations
            int hw = t + i * 512;
            float4 v = src[(size_t)hw * (NCH / 4)];
            unsigned k[4] = { __float_as_uint(v.x), __float_as_uint(v.y),
                              __float_as_uint(v.z), __float_as_uint(v.w) };
            vals[0 * STRIDE + hw] = k[0];
            vals[1 * STRIDE + hw] = k[1];
            vals[2 * STRIDE + hw] = k[2];
            vals[3 * STRIDE + hw] = k[3];
#pragma unroll
            for (int e = 0; e < 4; e++) {
                unsigned bin = mkey(k[e]) >> 24;
                unsigned m = __match_any_sync(FULLMASK, ((unsigned)e << 8) | bin);
                if (lane == (__ffs((int)m) - 1))
                    atomicAdd(&hist[e * HSTR + bin], (unsigned)__popc(m));
            }
        }
        if (warp < 2) {                      // tail: hw in [3072, 3136), fully valid
            int hw = t + 3072;
            float4 v = src[(size_t)hw * (NCH / 4)];
            unsigned k[4] = { __float_as_uint(v.x), __float_as_uint(v.y),
                              __float_as_uint(v.z), __float_as_uint(v.w) };
            vals[0 * STRIDE + hw] = k[0];
            vals[1 * STRIDE + hw] = k[1];
            vals[2 * STRIDE + hw] = k[2];
            vals[3 * STRIDE + hw] = k[3];
#pragma unroll
            for (int e = 0; e < 4; e++) {
                unsigned bin = mkey(k[e]) >> 24;
                unsigned m = __match_any_sync(FULLMASK, ((unsigned)e << 8) | bin);
                if (lane == (__ffs((int)m) - 1))
                    atomicAdd(&hist[e * HSTR + bin], (unsigned)__popc(m));
            }
        }
    }
    __syncthreads();

    // ---- per-channel selection ---------------------------------------------
    unsigned* rowU  = vals + w * STRIDE;
    const uint4* row4 = reinterpret_cast<const uint4*>(rowU);
    unsigned* bufA  = hist + w * HSTR;
    unsigned* bufB  = bufA + 256;
    unsigned* spare = bufA + 512;
    const int qBase = q * QQ;
    const int eBase = q * QELEM;

    int rT = 0, rB = 0;                      // live only in warp q==0
    int rT3 = 0, rB3 = 0, eqB = 0;

    // L0 walks: only q==0 (bufB is pre-zeroed for L1 by the init loop)
    if (q == 0) {
        int3 st = walk(bufA, 0, lane, KSEL);
        int3 sb = walk(bufA, 0, lane, RBRANK);
        rT = st.y; rB = sb.y;
        if (lane == 0) { spare[0] = (unsigned)st.x; spare[1] = (unsigned)sb.x; }
    }
    __syncthreads();
    const int selT = (int)spare[0];
    const int selB = (int)spare[1];

    // ---- L1: single full scan: sure-sums + candidate compaction + hist(B) --
    float sg = 0.f, sl = 0.f;
    unsigned cnt = 0;                        // compacted count (warp-uniform)
#pragma unroll 1
    for (int i = 0; i < SCAN_IT; i++) {
        int idx = i * 32 + lane;
        bool valid = idx < QQ;
        uint4 kv = valid ? row4[qBase + idx] : make_uint4(0u, 0u, 0u, 0u);
        unsigned ks[4] = {kv.x, kv.y, kv.z, kv.w};
#pragma unroll
        for (int e = 0; e < 4; e++) {
            unsigned bb = ks[e];
            unsigned kk = mkey(bb);
            int bin = (int)(kk >> 24);
            float v = __uint_as_float(bb);
            if (valid && bin > selT) sg += v;
            if (valid && bin < selB) sl += v;
            unsigned add = (valid && bin == selT ? 1u : 0u)
                         + (valid && bin == selB ? 0x10000u : 0u);
            if (add) atomicAdd(&bufB[(kk >> 16) & 0xFFu], add);
            unsigned bal = __ballot_sync(FULLMASK, add != 0u);
            if (add) {
                unsigned pos = cnt + __popc(bal & ((1u << lane) - 1u));
                rowU[eBase + pos] = bb;      // pos < read frontier: in-warp safe
            }
            cnt += (unsigned)__popc(bal);
        }
    }
    __syncthreads();

    // L1 walk (q0) overlapped with zeroing bufA (q1..3)
    if (q == 0) {
        int3 wt = walk(bufB, 0,  lane, rT);
        int3 wb = walk(bufB, 16, lane, rB);
        rT = wt.y; rB = wb.y;
        if (lane == 0) {
            spare[2] = ((unsigned)selT << 24) | ((unsigned)wt.x << 16);
            spare[3] = ((unsigned)selB << 24) | ((unsigned)wb.x << 16);
        }
    } else {
        for (int i = (q - 1) * 32 + lane; i < 256; i += 96) bufA[i] = 0;
    }
    __syncthreads();
    unsigned pfxT = spare[2], pfxB = spare[3];
    const int citers = (int)((cnt + 31u) >> 5);

    // ---- L2 over compact list (hist A) -------------------------------------
#pragma unroll 1
    for (int i = 0; i < citers; i++) {
        unsigned idx = (unsigned)(i * 32 + lane);
        if (idx < cnt) {
            unsigned kk = mkey(rowU[eBase + idx]);
            unsigned hi16 = kk >> 16;
            unsigned add = ((hi16 == (pfxT >> 16)) ? 1u : 0u)
                         + ((hi16 == (pfxB >> 16)) ? 0x10000u : 0u);
            if (add) atomicAdd(&bufA[(kk >> 8) & 0xFFu], add);
        }
    }
    __syncthreads();

    // L2 walk (q0) overlapped with zeroing bufB (q1..3)
    if (q == 0) {
        int3 wt = walk(bufA, 0,  lane, rT);
        int3 wb = walk(bufA, 16, lane, rB);
        rT = wt.y; rB = wb.y;
        if (lane == 0) {
            spare[2] = pfxT | ((unsigned)wt.x << 8);
            spare[3] = pfxB | ((unsigned)wb.x << 8);
        }
    } else {
        for (int i = (q - 1) * 32 + lane; i < 256; i += 96) bufB[i] = 0;
    }
    __syncthreads();
    pfxT = spare[2]; pfxB = spare[3];

    // ---- L3 over compact list (hist B) -------------------------------------
#pragma unroll 1
    for (int i = 0; i < citers; i++) {
        unsigned idx = (unsigned)(i * 32 + lane);
        if (idx < cnt) {
            unsigned kk = mkey(rowU[eBase + idx]);
            unsigned hi24 = kk >> 8;
            unsigned add = ((hi24 == (pfxT >> 8)) ? 1u : 0u)
                         + ((hi24 == (pfxB >> 8)) ? 0x10000u : 0u);
            if (add) atomicAdd(&bufB[kk & 0xFFu], add);
        }
    }
    __syncthreads();

    if (q == 0) {
        int3 wt = walk(bufB, 0,  lane, rT);
        int3 wb = walk(bufB, 16, lane, rB);
        rT3 = wt.y; rB3 = wb.y; eqB = wb.z;
        if (lane == 0) {
            spare[4] = __float_as_uint(key2f(pfxT | (unsigned)wt.x));
            spare[5] = __float_as_uint(key2f(pfxB | (unsigned)wb.x));
        }
    }
    __syncthreads();
    const float vT = __uint_as_float(spare[4]);
    const float vB = __uint_as_float(spare[5]);

    // ---- stats tail over compact list (float compares) ---------------------
#pragma unroll 1
    for (int i = 0; i < citers; i++) {
        unsigned idx = (unsigned)(i * 32 + lane);
        if (idx < cnt) {
            float v = __uint_as_float(rowU[eBase + idx]);
            if (v > vT) sg += v;
            if (v < vB) sl += v;
        }
    }
    sg = wredf(sg);
    sl = wredf(sl);

    float* accF = reinterpret_cast<float*>(spare + 6);
    if (lane == 0) {
        atomicAdd(&accF[0], sg);
        atomicAdd(&accF[1], sl);
    }
    __syncthreads();

    if (q == 0 && lane == 0) {
        // counts come free from the final walk ranks:
        int cg   = KSEL - rT3;               // strictly > vT
        int cGTb = RBRANK - rB3;             // strictly > vB
        int cl   = HWN - cGTb - eqB;         // strictly < vB
        float Sg = accF[0], Sl = accF[1];
        float xmax = (Sg + (float)(KSEL - cg) * vT) * (1.0f / (float)KSEL);
        float xmin = (Sl + (float)(KSEL - cl) * vB) * (ALPHA / (float)KSEL);
        out[b * NCH + c0 + w] = 0.5f * (xmax + xmin);
    }
}

extern "C" void kernel_launch(void* const* d_in, const int* in_sizes, int n_in,
                              void* d_out, int out_size)
{
    const float* x = (const float*)d_in[0];
    float* out = (float*)d_out;
    cudaFuncSetAttribute(wildcat_kernel,
                         cudaFuncAttributeMaxDynamicSharedMemorySize,
                         SMEM_WORDS * (int)sizeof(unsigned));
    wildcat_kernel<<<NBATCH * (NCH / CPB), 512, SMEM_WORDS * sizeof(unsigned)>>>(x, out);
}

// round 11
// speedup vs baseline: 18.5139x; 1.0830x over previous
#include <cuda_runtime.h>
#include <cuda_bf16.h>
#include <stdint.h>

#define FULLMASK 0xFFFFFFFFu

constexpr int HWN     = 3136;   // 56*56
constexpr int NCH     = 512;
constexpr int NBATCH  = 32;
constexpr int CPB     = 4;      // channels per block (4 warps per channel)
constexpr int KSEL    = 627;    // round(0.2*3136)
constexpr int RBRANK  = HWN - KSEL + 1;  // bottom-end rank from largest
constexpr int STRIDE  = 3140;   // smem row stride (u32), 16B aligned
constexpr int NQ      = HWN / 4;        // 784 uint4 per row
constexpr int QQ      = NQ / 4;         // 196 uint4 per warp quarter
constexpr int QELEM   = QQ * 4;         // 784 elements per quarter
constexpr int HSTR    = 528;    // 256 (bufA) + 256 (bufB) + 16 spare
constexpr int SMEM_WORDS = CPB * STRIDE + CPB * HSTR;
constexpr float ALPHA = 0.7f;

__device__ __forceinline__ float key2f(unsigned u) {
    return __uint_as_float((u & 0x80000000u) ? (u & 0x7FFFFFFFu) : ~u);
}
// branch-free monotone key from float bits
__device__ __forceinline__ unsigned mkey(unsigned b) {
    return b ^ ((unsigned)(((int)b) >> 31) | 0x80000000u);
}

__device__ __forceinline__ float wredf(float v) {
#pragma unroll
    for (int d = 16; d; d >>= 1) v += __shfl_xor_sync(FULLMASK, v, d);
    return v;
}

// per-channel barrier: 4 warps (128 threads), barrier id = channel+1
__device__ __forceinline__ void chbar(int id) {
    asm volatile("bar.sync %0, %1;" :: "r"(id), "r"(128) : "memory");
}

// Warp-parallel rank walk over a 256-bin histogram; rank r 1-based FROM THE
// LARGEST bin. Counts are ((hist[i] >> shift) & 0xFFFF).
// Returns (bin, rankInBin, countOfBin).
__device__ __forceinline__ int3 walk(const unsigned* hist, int shift, int lane, int r)
{
    unsigned c[8];
    int s = 0;
#pragma unroll
    for (int j = 0; j < 8; j++) {
        c[j] = (hist[lane * 8 + j] >> shift) & 0xFFFFu;
        s += (int)c[j];
    }
    int incl = s;                           // suffix-sum over lanes >= lane
#pragma unroll
    for (int d = 1; d < 32; d <<= 1) {
        int v = __shfl_down_sync(FULLMASK, incl, d);
        if (lane + d < 32) incl += v;
    }
    int hi = incl - s;
    bool sel = (hi < r) && (r <= hi + s);
    unsigned bal = __ballot_sync(FULLMASK, sel);
    int L = __ffs((int)bal) - 1;
    int bin = -1, rr = 0, cc = 0;
    if (lane == L) {
        int rloc = r - hi, cum = 0;
#pragma unroll
        for (int j = 7; j >= 0; j--) {
            if (bin < 0 && rloc <= cum + (int)c[j]) { bin = j; rr = rloc - cum; cc = (int)c[j]; }
            cum += (int)c[j];
        }
        bin += lane * 8;
    }
    bin = __shfl_sync(FULLMASK, bin, L);
    rr  = __shfl_sync(FULLMASK, rr,  L);
    cc  = __shfl_sync(FULLMASK, cc,  L);
    return make_int3(bin, rr, cc);
}

extern __shared__ unsigned smem[];

__global__ void __launch_bounds__(512, 3)
wildcat_kernel(const float* __restrict__ x, float* __restrict__ out)
{
    unsigned* vals = smem;                   // CPB * STRIDE (raw float bits)
    unsigned* hist = smem + CPB * STRIDE;    // CPB * HSTR

    const int t    = threadIdx.x;
    const int lane = t & 31;
    const int warp = t >> 5;                 // 0..15
    const int w    = warp >> 2;              // channel 0..3
    const int q    = warp & 3;               // quarter of the spatial row
    const int bar  = w + 1;                  // named barrier id for this channel
    const int b    = blockIdx.x >> 7;        // batch
    const int c0   = (blockIdx.x & 127) * CPB;

    for (int i = t; i < CPB * HSTR; i += 512) hist[i] = 0;
    __syncthreads();

    // ---- load + transpose + FUSED level-0 histogram (into bufA) ------------
    // For a fixed element slot e all lanes hold channel e => match on bin alone.
    {
        const float4* src = reinterpret_cast<const float4*>(
            x + (size_t)b * HWN * NCH + c0);
#pragma unroll 2
        for (int i = 0; i < 6; i++) {        // 6 full, unconditional iterations
            int hw = t + i * 512;
            float4 v = src[(size_t)hw * (NCH / 4)];
            unsigned k[4] = { __float_as_uint(v.x), __float_as_uint(v.y),
                              __float_as_uint(v.z), __float_as_uint(v.w) };
            vals[0 * STRIDE + hw] = k[0];
            vals[1 * STRIDE + hw] = k[1];
            vals[2 * STRIDE + hw] = k[2];
            vals[3 * STRIDE + hw] = k[3];
#pragma unroll
            for (int e = 0; e < 4; e++) {
                unsigned bin = mkey(k[e]) >> 24;
                unsigned m = __match_any_sync(FULLMASK, bin);
                if (lane == (__ffs((int)m) - 1))
                    atomicAdd(&hist[e * HSTR + bin], (unsigned)__popc(m));
            }
        }
        if (warp < 2) {                      // tail: hw in [3072, 3136), fully valid
            int hw = t + 3072;
            float4 v = src[(size_t)hw * (NCH / 4)];
            unsigned k[4] = { __float_as_uint(v.x), __float_as_uint(v.y),
                              __float_as_uint(v.z), __float_as_uint(v.w) };
            vals[0 * STRIDE + hw] = k[0];
            vals[1 * STRIDE + hw] = k[1];
            vals[2 * STRIDE + hw] = k[2];
            vals[3 * STRIDE + hw] = k[3];
#pragma unroll
            for (int e = 0; e < 4; e++) {
                unsigned bin = mkey(k[e]) >> 24;
                unsigned m = __match_any_sync(FULLMASK, bin);
                if (lane == (__ffs((int)m) - 1))
                    atomicAdd(&hist[e * HSTR + bin], (unsigned)__popc(m));
            }
        }
    }
    __syncthreads();                         // last block-wide barrier

    // ---- per-channel selection (channels fully decoupled from here) --------
    unsigned* rowU  = vals + w * STRIDE;
    const uint4* row4 = reinterpret_cast<const uint4*>(rowU);
    unsigned* bufA  = hist + w * HSTR;
    unsigned* bufB  = bufA + 256;
    unsigned* spare = bufA + 512;
    const int qBase = q * QQ;
    const int eBase = q * QELEM;

    int rT = 0;                              // live in q0
    int rB = 0;                              // live in q1

    // L0 walks: top on q0, bottom on q1 (independent chains)
    if (q == 0) {
        int3 st = walk(bufA, 0, lane, KSEL);
        rT = st.y;
        if (lane == 0) spare[0] = (unsigned)st.x;
    } else if (q == 1) {
        int3 sb = walk(bufA, 0, lane, RBRANK);
        rB = sb.y;
        if (lane == 0) spare[1] = (unsigned)sb.x;
    }
    chbar(bar);
    const int selT = (int)spare[0];
    const int selB = (int)spare[1];

    // ---- L1: single full scan: sure-sums + compaction + hist(B) ------------
    float sg = 0.f, sl = 0.f;
    unsigned cnt = 0;                        // compacted count (warp-uniform)
#pragma unroll 1
    for (int i = 0; i < 7; i++) {
        const bool tailIt = (i == 6);
        const bool valid = !tailIt || (lane < QQ - 192);
        uint4 kv = valid ? row4[qBase + i * 32 + lane] : make_uint4(0u, 0u, 0u, 0u);
        unsigned ks[4] = {kv.x, kv.y, kv.z, kv.w};
#pragma unroll
        for (int e = 0; e < 4; e++) {
            unsigned bb = ks[e];
            unsigned kk = mkey(bb);
            int bin = (int)(kk >> 24);
            float v = __uint_as_float(bb);
            if (valid && bin > selT) sg += v;
            if (valid && bin < selB) sl += v;
            unsigned add = (valid && bin == selT ? 1u : 0u)
                         + (valid && bin == selB ? 0x10000u : 0u);
            if (add) atomicAdd(&bufB[(kk >> 16) & 0xFFu], add);
            unsigned bal = __ballot_sync(FULLMASK, add != 0u);
            if (add) {
                unsigned pos = cnt + __popc(bal & ((1u << lane) - 1u));
                rowU[eBase + pos] = bb;      // pos < read frontier: in-warp safe
            }
            cnt += (unsigned)__popc(bal);
        }
    }
    chbar(bar);

    // L1 walks (q0 top / q1 bottom) overlapped with zeroing bufA (q2/q3)
    if (q == 0) {
        int3 wt = walk(bufB, 0, lane, rT);
        rT = wt.y;
        if (lane == 0) spare[2] = ((unsigned)selT << 24) | ((unsigned)wt.x << 16);
    } else if (q == 1) {
        int3 wb = walk(bufB, 16, lane, rB);
        rB = wb.y;
        if (lane == 0) spare[3] = ((unsigned)selB << 24) | ((unsigned)wb.x << 16);
    } else {
        for (int i = (q - 2) * 32 + lane; i < 256; i += 64) bufA[i] = 0;
    }
    chbar(bar);
    unsigned pfxT = spare[2], pfxB = spare[3];
    const int citers = (int)((cnt + 31u) >> 5);

    // ---- L2 over compact list (hist A) -------------------------------------
#pragma unroll 1
    for (int i = 0; i < citers; i++) {
        unsigned idx = (unsigned)(i * 32 + lane);
        if (idx < cnt) {
            unsigned kk = mkey(rowU[eBase + idx]);
            unsigned hi16 = kk >> 16;
            unsigned add = ((hi16 == (pfxT >> 16)) ? 1u : 0u)
                         + ((hi16 == (pfxB >> 16)) ? 0x10000u : 0u);
            if (add) atomicAdd(&bufA[(kk >> 8) & 0xFFu], add);
        }
    }
    chbar(bar);

    if (q == 0) {
        int3 wt = walk(bufA, 0, lane, rT);
        rT = wt.y;
        if (lane == 0) spare[2] = pfxT | ((unsigned)wt.x << 8);
    } else if (q == 1) {
        int3 wb = walk(bufA, 16, lane, rB);
        rB = wb.y;
        if (lane == 0) spare[3] = pfxB | ((unsigned)wb.x << 8);
    } else {
        for (int i = (q - 2) * 32 + lane; i < 256; i += 64) bufB[i] = 0;
    }
    chbar(bar);
    pfxT = spare[2]; pfxB = spare[3];

    // ---- L3 over compact list (hist B) -------------------------------------
#pragma unroll 1
    for (int i = 0; i < citers; i++) {
        unsigned idx = (unsigned)(i * 32 + lane);
        if (idx < cnt) {
            unsigned kk = mkey(rowU[eBase + idx]);
            unsigned hi24 = kk >> 8;
            unsigned add = ((hi24 == (pfxT >> 8)) ? 1u : 0u)
                         + ((hi24 == (pfxB >> 8)) ? 0x10000u : 0u);
            if (add) atomicAdd(&bufB[kk & 0xFFu], add);
        }
    }
    chbar(bar);

    if (q == 0) {
        int3 wt = walk(bufB, 0, lane, rT);
        if (lane == 0) {
            spare[4] = __float_as_uint(key2f(pfxT | (unsigned)wt.x));
            spare[6] = (unsigned)wt.y;           // rT3
        }
    } else if (q == 1) {
        int3 wb = walk(bufB, 16, lane, rB);
        if (lane == 0) {
            spare[5] = __float_as_uint(key2f(pfxB | (unsigned)wb.x));
            spare[7] = (unsigned)(wb.y - wb.z);  // rB3 - eqB  (FIX: minus, not plus)
        }
    }
    chbar(bar);
    const float vT = __uint_as_float(spare[4]);
    const float vB = __uint_as_float(spare[5]);

    // ---- stats tail over compact list (float compares) ---------------------
#pragma unroll 1
    for (int i = 0; i < citers; i++) {
        unsigned idx = (unsigned)(i * 32 + lane);
        if (idx < cnt) {
            float v = __uint_as_float(rowU[eBase + idx]);
            if (v > vT) sg += v;
            if (v < vB) sl += v;
        }
    }
    sg = wredf(sg);
    sl = wredf(sl);

    float* accF = reinterpret_cast<float*>(spare + 8);
    if (lane == 0) {
        atomicAdd(&accF[0], sg);
        atomicAdd(&accF[1], sl);
    }
    chbar(bar);

    if (q == 0 && lane == 0) {
        int rT3  = (int)spare[6];
        int rbme = (int)spare[7];            // rB3 - eqB (signed)
        int cg   = KSEL - rT3;               // strictly > vT
        int cl   = HWN - RBRANK + rbme;      // strictly < vB
        float Sg = accF[0], Sl = accF[1];
        float xmax = (Sg + (float)(KSEL - cg) * vT) * (1.0f / (float)KSEL);
        float xmin = (Sl + (float)(KSEL - cl) * vB) * (ALPHA / (float)KSEL);
        out[b * NCH + c0 + w] = 0.5f * (xmax + xmin);
    }
}

extern "C" void kernel_launch(void* const* d_in, const int* in_sizes, int n_in,
                              void* d_out, int out_size)
{
    const float* x = (const float*)d_in[0];
    float* out = (float*)d_out;
    cudaFuncSetAttribute(wildcat_kernel,
                         cudaFuncAttributeMaxDynamicSharedMemorySize,
                         SMEM_WORDS * (int)sizeof(unsigned));
    wildcat_kernel<<<NBATCH * (NCH / CPB), 512, SMEM_WORDS * sizeof(unsigned)>>>(x, out);
}